// round 8
// baseline (speedup 1.0000x reference)
#include <cuda_runtime.h>

// Convolution_22600117912286: continuous convolution with Gaussian radial basis.
// out[z,a,i] = (1/sqrt(n_norm)) * sum_b sum_c exp(-((d_ab - c*w)/w)^2) * G[z,b,c,i]
//   where G[z,b,c,i] = sum_j W[c,i,j] * features[z,b,j]
// Shapes: B=2, N=1024, D_IN=8, D_OUT=8, C=32, R_MAX=3.5, w=3.5/31.
//
// R6 changes vs R4:
//  - prep_G rewritten: W row in registers, features broadcast via smem,
//    fully coalesced stores (was 21.2us latency-bound -> ~2.5us).
//  - SPLIT 4->8: 512 blocks, wave imbalance 2.0 -> 1.33.
//  - k-window padded with zero rows (-4..35): no predicates in tap loop.
//  - packed fma.rn.f32x2 accumulators: 72 scalar FFMA/pair -> 36 FFMA2.

#define BATCH   2
#define NPTS    1024
#define DIN     8
#define DOUT    8
#define NC      32
#define RMAXF   3.5f
#define TILE_A  32
#define SPLIT   8
#define B_TILE  16
#define KPAD    4
#define KROWS   (NC + 2 * KPAD)   // 40 rows of k per b (rows 0..3 and 36..39 are zero)
#define GSTRIDE 12                // floats per (b,k) row: 8 data + 4 pad = 48B

// scratch (no allocations allowed -> __device__ globals)
__device__ float g_G[BATCH * NPTS * NC * DOUT];                 // 2 MB
__device__ float g_partial[SPLIT * BATCH * NPTS * DOUT];        // 512 KB

// packed f32x2 helpers (FFMA2: not emittable from plain C++, PTX only)
__device__ __forceinline__ void ffma2(unsigned long long& acc,
                                      unsigned long long g,
                                      unsigned long long w)
{
    asm("fma.rn.f32x2 %0, %1, %2, %0;" : "+l"(acc) : "l"(g), "l"(w));
}
__device__ __forceinline__ unsigned long long pack2(float v)
{
    unsigned long long r;
    asm("mov.b64 %0, {%1, %1};" : "=l"(r) : "r"(__float_as_int(v)));
    return r;
}

// ---------------------------------------------------------------------------
// Kernel 1: G[z,b,c,i] = scale * sum_j W[c,i,j] * f[z,b,j]
// Block = 32 zb rows x 256 output columns (c*8+i). W row lives in registers,
// features broadcast from smem, stores fully coalesced.
// ---------------------------------------------------------------------------
__global__ __launch_bounds__(256)
void prep_G_kernel(const float* __restrict__ feat,
                   const float* __restrict__ W,
                   const int* __restrict__ n_norm)
{
    __shared__ __align__(16) float sf[32 * DIN];    // 32 zb x 8 features

    const int tid = threadIdx.x;
    const int zb0 = blockIdx.x * 32;

    sf[tid] = feat[zb0 * DIN + tid];                // 256 floats, coalesced
    __syncthreads();

    const float scale = rsqrtf((float)(*n_norm));

    // this thread's output column co = c*8 + i; its W row is W[co*8 .. co*8+7]
    const float4 wa = *reinterpret_cast<const float4*>(W + tid * DIN);
    const float4 wb = *reinterpret_cast<const float4*>(W + tid * DIN + 4);
    const float w0 = wa.x * scale, w1 = wa.y * scale, w2 = wa.z * scale, w3 = wa.w * scale;
    const float w4 = wb.x * scale, w5 = wb.y * scale, w6 = wb.z * scale, w7 = wb.w * scale;

#pragma unroll 8
    for (int b = 0; b < 32; ++b) {
        float4 fa = *reinterpret_cast<const float4*>(&sf[b * DIN]);      // broadcast
        float4 fb = *reinterpret_cast<const float4*>(&sf[b * DIN + 4]);
        float s = w0 * fa.x;
        s = fmaf(w1, fa.y, s);
        s = fmaf(w2, fa.z, s);
        s = fmaf(w3, fa.w, s);
        s = fmaf(w4, fb.x, s);
        s = fmaf(w5, fb.y, s);
        s = fmaf(w6, fb.z, s);
        s = fmaf(w7, fb.w, s);
        g_G[(size_t)(zb0 + b) * (NC * DOUT) + tid] = s;                  // coalesced
    }
}

// ---------------------------------------------------------------------------
// Kernel 2: main pairwise contraction.
// Block = (z, a-tile of 32, b-split of 128). Thread (a_local, lane_b).
// Gaussian basis via peak-anchored multiplicative recurrence over a +/-4
// center window; out-of-range taps read permanently-zero padded smem rows.
// ---------------------------------------------------------------------------
__global__ __launch_bounds__(256)
void conv_kernel(const float* __restrict__ geom)
{
    __shared__ __align__(16) float  sG[B_TILE * KROWS * GSTRIDE];  // 7680 f = 30 KB
    __shared__ float4 sgeo[B_TILE];

    const int tid     = threadIdx.x;
    const int z       = blockIdx.z;
    const int a0      = blockIdx.x * TILE_A;
    const int bsplit0 = blockIdx.y * (NPTS / SPLIT);
    const int a_local = tid & (TILE_A - 1);
    const int lane_b  = tid >> 5;                  // 0..7

    // zero the whole tile once; pad rows are never written afterwards
#pragma unroll
    for (int q = tid; q < B_TILE * KROWS * GSTRIDE; q += 256) sG[q] = 0.0f;

    const int   a  = a0 + a_local;
    const float ax = geom[(z * NPTS + a) * 3 + 0];
    const float ay = geom[(z * NPTS + a) * 3 + 1];
    const float az = geom[(z * NPTS + a) * 3 + 2];

    const float INV_W = (float)(NC - 1) / RMAXF;   // 31/3.5
    const float E2    = 0.13533528323661270f;      // exp(-2)

    unsigned long long A0 = 0ull, A1 = 0ull, A2 = 0ull, A3 = 0ull;

    const int NT = (NPTS / SPLIT) / B_TILE;        // 8 tiles
    for (int t = 0; t < NT; ++t) {
        const int bt = bsplit0 + t * B_TILE;
        __syncthreads();                           // protect sG/sgeo from last iter

        // --- stage geometry tile ---
        if (tid < B_TILE) {
            const float* gp = geom + (size_t)(z * NPTS + bt + tid) * 3;
            sgeo[tid] = make_float4(gp[0], gp[1], gp[2], 0.f);
        }
        // --- stage G tile: 16b x 32k x 8i, coalesced gmem -> padded smem ---
        const float4* src = reinterpret_cast<const float4*>(
            g_G + (size_t)((z * NPTS + bt) * NC) * DOUT);
#pragma unroll
        for (int it = 0; it < 4; ++it) {
            int q = tid + it * 256;                // 0..1023 float4s
            float4 v  = src[q];
            int   i4  = q & 1;
            int   k   = (q >> 1) & (NC - 1);
            int   bl  = q >> 6;
            *reinterpret_cast<float4*>(
                &sG[(bl * KROWS + k + KPAD) * GSTRIDE + i4 * 4]) = v;
        }
        __syncthreads();

#pragma unroll
        for (int half = 0; half < 2; ++half) {
            const int bl = lane_b + half * 8;
            float4 gb = sgeo[bl];
            float dx = ax - gb.x, dy = ay - gb.y, dz = az - gb.z;
            float d2 = fmaf(dx, dx, fmaf(dy, dy, fmaf(dz, dz, 1e-12f)));
            float u0 = sqrtf(d2) * INV_W;          // distance in width units
            int   k0 = __float2int_rn(u0);
            k0 = min(k0, NC - 1);                  // u0 >= 0 so k0 >= 0
            float p  = u0 - (float)k0;             // in [-0.5, 0.5] unless past last center
            float pc = fminf(p, 4.0f);
            float b0 = (p < 4.0f) ? __expf(-pc * pc) : 0.0f;
            float ru = __expf(fmaf( 2.0f, pc, -1.0f));
            float rd = __expf(fmaf(-2.0f, pc, -1.0f));

            // weights for centers k0-4 .. k0+4 (truncated terms <= exp(-12.25))
            float wgt[9];
            wgt[4] = b0;
            float bb = b0, r = ru;
#pragma unroll
            for (int s = 1; s <= 4; ++s) { bb *= r; r *= E2; wgt[4 + s] = bb; }
            bb = b0; r = rd;
#pragma unroll
            for (int s = 1; s <= 4; ++s) { bb *= r; r *= E2; wgt[4 - s] = bb; }

            const float* gbase = &sG[(bl * KROWS + k0 + KPAD - 4) * GSTRIDE];
#pragma unroll
            for (int s = 0; s < 9; ++s) {
                ulonglong2 gA = *reinterpret_cast<const ulonglong2*>(gbase + s * GSTRIDE);
                ulonglong2 gB = *reinterpret_cast<const ulonglong2*>(gbase + s * GSTRIDE + 4);
                unsigned long long wp = pack2(wgt[s]);
                ffma2(A0, gA.x, wp);
                ffma2(A1, gA.y, wp);
                ffma2(A2, gB.x, wp);
                ffma2(A3, gB.y, wp);
            }
        }
    }
    __syncthreads();                               // last tile's reads done

    // --- deterministic in-block reduction over the 8 lane_b partials ---
    float* sred = sG;                              // reuse smem (2048 floats needed)
    {
        ulonglong2* sp64 = reinterpret_cast<ulonglong2*>(sred);
        sp64[(a_local * 8 + lane_b) * 2 + 0] = make_ulonglong2(A0, A1);
        sp64[(a_local * 8 + lane_b) * 2 + 1] = make_ulonglong2(A2, A3);
    }
    __syncthreads();
    {
        int al = tid >> 3;          // 0..31
        int i  = tid & 7;           // 0..7
        float s = 0.0f;
#pragma unroll
        for (int lb = 0; lb < 8; ++lb)
            s += sred[(al * 8 + lb) * 8 + i];
        g_partial[((blockIdx.y * BATCH + z) * NPTS + (a0 + al)) * DOUT + i] = s;
    }
}

// ---------------------------------------------------------------------------
// Kernel 3: sum the SPLIT partials into the output (deterministic, no atomics)
// ---------------------------------------------------------------------------
__global__ __launch_bounds__(256)
void reduce_kernel(float* __restrict__ out)
{
    int t = blockIdx.x * blockDim.x + threadIdx.x;
    if (t < BATCH * NPTS * DOUT) {
        float s = 0.0f;
#pragma unroll
        for (int sp = 0; sp < SPLIT; ++sp)
            s += g_partial[sp * (BATCH * NPTS * DOUT) + t];
        out[t] = s;
    }
}

extern "C" void kernel_launch(void* const* d_in, const int* in_sizes, int n_in,
                              void* d_out, int out_size)
{
    const float* features = (const float*)d_in[0];   // [2,1024,8]
    const float* geometry = (const float*)d_in[1];   // [2,1024,3]
    const float* W        = (const float*)d_in[2];   // [32,8,8]
    const int*   n_norm   = (const int*)d_in[3];     // scalar
    float*       out      = (float*)d_out;           // [2,1024,8]

    prep_G_kernel<<<(BATCH * NPTS) / 32, 256>>>(features, W, n_norm);
    conv_kernel<<<dim3(NPTS / TILE_A, SPLIT, BATCH), 256>>>(geometry);
    reduce_kernel<<<(BATCH * NPTS * DOUT + 255) / 256, 256>>>(out);
}

// round 9
// speedup vs baseline: 1.0095x; 1.0095x over previous
#include <cuda_runtime.h>

// Convolution_22600117912286: continuous convolution with Gaussian radial basis.
// out[z,a,i] = (1/sqrt(n_norm)) * sum_b sum_c exp(-((d_ab - c*w)/w)^2) * G[z,b,c,i]
//   where G[z,b,c,i] = sum_j W[c,i,j] * features[z,b,j]
// Shapes: B=2, N=1024, D_IN=8, D_OUT=8, C=32, R_MAX=3.5, w=3.5/31.
//
// R6 changes vs R4:
//  - prep_G rewritten: W row in registers, features broadcast via smem,
//    fully coalesced stores (was 21.2us latency-bound -> ~2.5us).
//  - SPLIT 4->8: 512 blocks, wave imbalance 2.0 -> 1.33.
//  - k-window padded with zero rows (-4..35): no predicates in tap loop.
//  - packed fma.rn.f32x2 accumulators: 72 scalar FFMA/pair -> 36 FFMA2.

#define BATCH   2
#define NPTS    1024
#define DIN     8
#define DOUT    8
#define NC      32
#define RMAXF   3.5f
#define TILE_A  32
#define SPLIT   8
#define B_TILE  16
#define KPAD    4
#define KROWS   (NC + 2 * KPAD)   // 40 rows of k per b (rows 0..3 and 36..39 are zero)
#define GSTRIDE 12                // floats per (b,k) row: 8 data + 4 pad = 48B

// scratch (no allocations allowed -> __device__ globals)
__device__ float g_G[BATCH * NPTS * NC * DOUT];                 // 2 MB
__device__ float g_partial[SPLIT * BATCH * NPTS * DOUT];        // 512 KB

// packed f32x2 helpers (FFMA2: not emittable from plain C++, PTX only)
__device__ __forceinline__ void ffma2(unsigned long long& acc,
                                      unsigned long long g,
                                      unsigned long long w)
{
    asm("fma.rn.f32x2 %0, %1, %2, %0;" : "+l"(acc) : "l"(g), "l"(w));
}
__device__ __forceinline__ unsigned long long pack2(float v)
{
    unsigned long long r;
    asm("mov.b64 %0, {%1, %1};" : "=l"(r) : "r"(__float_as_int(v)));
    return r;
}

// ---------------------------------------------------------------------------
// Kernel 1: G[z,b,c,i] = scale * sum_j W[c,i,j] * f[z,b,j]
// Block = 32 zb rows x 256 output columns (c*8+i). W row lives in registers,
// features broadcast from smem, stores fully coalesced.
// ---------------------------------------------------------------------------
__global__ __launch_bounds__(256)
void prep_G_kernel(const float* __restrict__ feat,
                   const float* __restrict__ W,
                   const int* __restrict__ n_norm)
{
    __shared__ __align__(16) float sf[32 * DIN];    // 32 zb x 8 features

    const int tid = threadIdx.x;
    const int zb0 = blockIdx.x * 32;

    sf[tid] = feat[zb0 * DIN + tid];                // 256 floats, coalesced
    __syncthreads();

    const float scale = rsqrtf((float)(*n_norm));

    // this thread's output column co = c*8 + i; its W row is W[co*8 .. co*8+7]
    const float4 wa = *reinterpret_cast<const float4*>(W + tid * DIN);
    const float4 wb = *reinterpret_cast<const float4*>(W + tid * DIN + 4);
    const float w0 = wa.x * scale, w1 = wa.y * scale, w2 = wa.z * scale, w3 = wa.w * scale;
    const float w4 = wb.x * scale, w5 = wb.y * scale, w6 = wb.z * scale, w7 = wb.w * scale;

#pragma unroll 8
    for (int b = 0; b < 32; ++b) {
        float4 fa = *reinterpret_cast<const float4*>(&sf[b * DIN]);      // broadcast
        float4 fb = *reinterpret_cast<const float4*>(&sf[b * DIN + 4]);
        float s = w0 * fa.x;
        s = fmaf(w1, fa.y, s);
        s = fmaf(w2, fa.z, s);
        s = fmaf(w3, fa.w, s);
        s = fmaf(w4, fb.x, s);
        s = fmaf(w5, fb.y, s);
        s = fmaf(w6, fb.z, s);
        s = fmaf(w7, fb.w, s);
        g_G[(size_t)(zb0 + b) * (NC * DOUT) + tid] = s;                  // coalesced
    }
}

// ---------------------------------------------------------------------------
// Kernel 2: main pairwise contraction.
// Block = (z, a-tile of 32, b-split of 128). Thread (a_local, lane_b).
// Gaussian basis via peak-anchored multiplicative recurrence over a +/-4
// center window; out-of-range taps read permanently-zero padded smem rows.
// ---------------------------------------------------------------------------
__global__ __launch_bounds__(256)
void conv_kernel(const float* __restrict__ geom)
{
    __shared__ __align__(16) float  sG[B_TILE * KROWS * GSTRIDE];  // 7680 f = 30 KB
    __shared__ float4 sgeo[B_TILE];

    const int tid     = threadIdx.x;
    const int z       = blockIdx.z;
    const int a0      = blockIdx.x * TILE_A;
    const int bsplit0 = blockIdx.y * (NPTS / SPLIT);
    const int a_local = tid & (TILE_A - 1);
    const int lane_b  = tid >> 5;                  // 0..7

    // zero the whole tile once; pad rows are never written afterwards
#pragma unroll
    for (int q = tid; q < B_TILE * KROWS * GSTRIDE; q += 256) sG[q] = 0.0f;

    const int   a  = a0 + a_local;
    const float ax = geom[(z * NPTS + a) * 3 + 0];
    const float ay = geom[(z * NPTS + a) * 3 + 1];
    const float az = geom[(z * NPTS + a) * 3 + 2];

    const float INV_W = (float)(NC - 1) / RMAXF;   // 31/3.5
    const float E2    = 0.13533528323661270f;      // exp(-2)

    unsigned long long A0 = 0ull, A1 = 0ull, A2 = 0ull, A3 = 0ull;

    const int NT = (NPTS / SPLIT) / B_TILE;        // 8 tiles
    for (int t = 0; t < NT; ++t) {
        const int bt = bsplit0 + t * B_TILE;
        __syncthreads();                           // protect sG/sgeo from last iter

        // --- stage geometry tile ---
        if (tid < B_TILE) {
            const float* gp = geom + (size_t)(z * NPTS + bt + tid) * 3;
            sgeo[tid] = make_float4(gp[0], gp[1], gp[2], 0.f);
        }
        // --- stage G tile: 16b x 32k x 8i, coalesced gmem -> padded smem ---
        const float4* src = reinterpret_cast<const float4*>(
            g_G + (size_t)((z * NPTS + bt) * NC) * DOUT);
#pragma unroll
        for (int it = 0; it < 4; ++it) {
            int q = tid + it * 256;                // 0..1023 float4s
            float4 v  = src[q];
            int   i4  = q & 1;
            int   k   = (q >> 1) & (NC - 1);
            int   bl  = q >> 6;
            *reinterpret_cast<float4*>(
                &sG[(bl * KROWS + k + KPAD) * GSTRIDE + i4 * 4]) = v;
        }
        __syncthreads();

#pragma unroll
        for (int half = 0; half < 2; ++half) {
            const int bl = lane_b + half * 8;
            float4 gb = sgeo[bl];
            float dx = ax - gb.x, dy = ay - gb.y, dz = az - gb.z;
            float d2 = fmaf(dx, dx, fmaf(dy, dy, fmaf(dz, dz, 1e-12f)));
            float u0 = sqrtf(d2) * INV_W;          // distance in width units
            int   k0 = __float2int_rn(u0);
            k0 = min(k0, NC - 1);                  // u0 >= 0 so k0 >= 0
            float p  = u0 - (float)k0;             // in [-0.5, 0.5] unless past last center
            float pc = fminf(p, 4.0f);
            float b0 = (p < 4.0f) ? __expf(-pc * pc) : 0.0f;
            float ru = __expf(fmaf( 2.0f, pc, -1.0f));
            float rd = __expf(fmaf(-2.0f, pc, -1.0f));

            // weights for centers k0-4 .. k0+4 (truncated terms <= exp(-12.25))
            float wgt[9];
            wgt[4] = b0;
            float bb = b0, r = ru;
#pragma unroll
            for (int s = 1; s <= 4; ++s) { bb *= r; r *= E2; wgt[4 + s] = bb; }
            bb = b0; r = rd;
#pragma unroll
            for (int s = 1; s <= 4; ++s) { bb *= r; r *= E2; wgt[4 - s] = bb; }

            const float* gbase = &sG[(bl * KROWS + k0 + KPAD - 4) * GSTRIDE];
#pragma unroll
            for (int s = 0; s < 9; ++s) {
                ulonglong2 gA = *reinterpret_cast<const ulonglong2*>(gbase + s * GSTRIDE);
                ulonglong2 gB = *reinterpret_cast<const ulonglong2*>(gbase + s * GSTRIDE + 4);
                unsigned long long wp = pack2(wgt[s]);
                ffma2(A0, gA.x, wp);
                ffma2(A1, gA.y, wp);
                ffma2(A2, gB.x, wp);
                ffma2(A3, gB.y, wp);
            }
        }
    }
    __syncthreads();                               // last tile's reads done

    // --- deterministic in-block reduction over the 8 lane_b partials ---
    float* sred = sG;                              // reuse smem (2048 floats needed)
    {
        ulonglong2* sp64 = reinterpret_cast<ulonglong2*>(sred);
        sp64[(a_local * 8 + lane_b) * 2 + 0] = make_ulonglong2(A0, A1);
        sp64[(a_local * 8 + lane_b) * 2 + 1] = make_ulonglong2(A2, A3);
    }
    __syncthreads();
    {
        int al = tid >> 3;          // 0..31
        int i  = tid & 7;           // 0..7
        float s = 0.0f;
#pragma unroll
        for (int lb = 0; lb < 8; ++lb)
            s += sred[(al * 8 + lb) * 8 + i];
        g_partial[((blockIdx.y * BATCH + z) * NPTS + (a0 + al)) * DOUT + i] = s;
    }
}

// ---------------------------------------------------------------------------
// Kernel 3: sum the SPLIT partials into the output (deterministic, no atomics)
// ---------------------------------------------------------------------------
__global__ __launch_bounds__(256)
void reduce_kernel(float* __restrict__ out)
{
    int t = blockIdx.x * blockDim.x + threadIdx.x;
    if (t < BATCH * NPTS * DOUT) {
        float s = 0.0f;
#pragma unroll
        for (int sp = 0; sp < SPLIT; ++sp)
            s += g_partial[sp * (BATCH * NPTS * DOUT) + t];
        out[t] = s;
    }
}

extern "C" void kernel_launch(void* const* d_in, const int* in_sizes, int n_in,
                              void* d_out, int out_size)
{
    const float* features = (const float*)d_in[0];   // [2,1024,8]
    const float* geometry = (const float*)d_in[1];   // [2,1024,3]
    const float* W        = (const float*)d_in[2];   // [32,8,8]
    const int*   n_norm   = (const int*)d_in[3];     // scalar
    float*       out      = (float*)d_out;           // [2,1024,8]

    prep_G_kernel<<<(BATCH * NPTS) / 32, 256>>>(features, W, n_norm);
    conv_kernel<<<dim3(NPTS / TILE_A, SPLIT, BATCH), 256>>>(geometry);
    reduce_kernel<<<(BATCH * NPTS * DOUT + 255) / 256, 256>>>(out);
}